// round 8
// baseline (speedup 1.0000x reference)
#include <cuda_runtime.h>
#include <cuda_bf16.h>
#include <cstdint>

// ChamferDistance: z-bucketed + block-uniform windowed dense NN + exact fixup.
// Stage 1: counting-bucketize each (set,batch) by z (256 uniform buckets),
//          points stored transformed: (-2x,-2y,-2z,||p||^2).
// Stage 2: per block of 256 sorted queries, pick a bucket-aligned ref window
//          (<=1024 refs) ONCE, then R3-style dense f32x2-FMA scan over smem.
//          Per-query analytic soundness check -> flag rare misses.
// Stage 3: flagged queries brute-forced exactly.
// Stage 4: flat deterministic sum.

#define BATCH    16
#define NPTS     4096
#define NBUCK    256
#define ZLO      (-4.6f)
#define ZHI      (4.6f)
#define BW       ((ZHI - ZLO) / NBUCK)
#define INVBW    ((float)NBUCK / (ZHI - ZLO))

#define BTHREADS 512
#define WTHREADS 128
#define QPT      2
#define QPB      (WTHREADS * QPT)             // 256 queries per window block
#define WCHUNKS  (NPTS / QPB)                 // 16
#define MAXW     1024                         // window refs (<= smem capacity)
#define WPAIR    (MAXW / 2)                   // 512 pairs -> 16 KB
#define FTHREADS 256
#define TOTQ     (2 * BATCH * NPTS)           // 131072
#define R1BLOCKS 128
#define FINF     __int_as_float(0x7f800000)

__device__ float4        g_pts[2 * BATCH][NPTS];
__device__ int           g_start[2 * BATCH][NBUCK + 1];
__device__ float         g_min[2 * BATCH][NPTS];
__device__ unsigned char g_flag[2 * BATCH][NPTS];
__device__ float         g_bsum[R1BLOCKS];

__device__ __forceinline__ int bucket_of(float z) {
    int b = (int)floorf((z - ZLO) * INVBW);
    return min(max(b, 0), NBUCK - 1);
}

// ---------- packed f32x2 helpers ----------
__device__ __forceinline__ unsigned long long ffma2(unsigned long long a,
                                                    unsigned long long b,
                                                    unsigned long long c) {
    unsigned long long d;
    asm("fma.rn.f32x2 %0, %1, %2, %3;" : "=l"(d) : "l"(a), "l"(b), "l"(c));
    return d;
}
__device__ __forceinline__ unsigned long long pack2(float lo, float hi) {
    unsigned long long d;
    asm("mov.b64 %0, {%1, %2};" : "=l"(d) : "r"(__float_as_uint(lo)), "r"(__float_as_uint(hi)));
    return d;
}
__device__ __forceinline__ void unpack2(unsigned long long v, float& lo, float& hi) {
    unsigned int l, h;
    asm("mov.b64 {%0, %1}, %2;" : "=r"(l), "=r"(h) : "l"(v));
    lo = __uint_as_float(l);
    hi = __uint_as_float(h);
}

// ---------------- stage 1: bucketize ----------------------------------------
__global__ __launch_bounds__(BTHREADS)
void chamfer_bucketize_kernel(const float* __restrict__ x,
                              const float* __restrict__ y) {
    extern __shared__ float sm[];                 // px | py | pz
    float* px = sm;
    float* py = sm + NPTS;
    float* pz = sm + 2 * NPTS;
    __shared__ int cnt[NBUCK];
    __shared__ int scan[NBUCK];
    __shared__ int off[NBUCK];

    const int b = blockIdx.x, set = blockIdx.y;
    const float* src = (set == 0 ? x : y) + (size_t)b * NPTS * 3;
    const int sb = set * BATCH + b;
    const int tid = threadIdx.x;

    for (int i = tid; i < NBUCK; i += BTHREADS) cnt[i] = 0;
    __syncthreads();
    #pragma unroll
    for (int i = tid; i < NPTS; i += BTHREADS) {
        float a = src[3 * i], c = src[3 * i + 1], d = src[3 * i + 2];
        px[i] = a; py[i] = c; pz[i] = d;
        atomicAdd(&cnt[bucket_of(d)], 1);
    }
    __syncthreads();
    if (tid < NBUCK) scan[tid] = cnt[tid];
    #pragma unroll
    for (int o = 1; o < NBUCK; o <<= 1) {
        __syncthreads();
        int v = (tid < NBUCK && tid >= o) ? scan[tid - o] : 0;
        __syncthreads();
        if (tid < NBUCK) scan[tid] += v;
    }
    __syncthreads();
    if (tid < NBUCK) {
        int st = scan[tid] - cnt[tid];
        off[tid] = st;
        g_start[sb][tid] = st;
        if (tid == 0) g_start[sb][NBUCK] = NPTS;
    }
    __syncthreads();
    #pragma unroll
    for (int i = tid; i < NPTS; i += BTHREADS) {
        float a = px[i], c = py[i], d = pz[i];
        int pos = atomicAdd(&off[bucket_of(d)], 1);
        g_pts[sb][pos] = make_float4(-2.f * a, -2.f * c, -2.f * d,
                                     fmaf(a, a, fmaf(c, c, d * d)));
    }
}

// ---------------- stage 2: windowed dense scan --------------------------------
__global__ __launch_bounds__(WTHREADS)
void chamfer_window_kernel() {
    __shared__ float4 shA[WPAIR];   // (-2x0,-2x1,-2y0,-2y1)
    __shared__ float4 shB[WPAIR];   // (-2z0,-2z1, n0,  n1)
    __shared__ int sstart[NBUCK + 1];

    const int chunk = blockIdx.x, b = blockIdx.y, dir = blockIdx.z;
    const int qsb = dir * BATCH + b;              // queries: x for dir0, y for dir1
    const int rsb = (1 - dir) * BATCH + b;
    const float4* __restrict__ refs = g_pts[rsb];
    const int tid = threadIdx.x;

    for (int i = tid; i <= NBUCK; i += WTHREADS) sstart[i] = g_start[rsb][i];
    __syncthreads();

    const int qbase = chunk * QPB;
    // Block query bucket span (bucketized order is bucket-monotone).
    const float zfirst = -0.5f * ((const float*)&g_pts[qsb][qbase])[2];
    const float zlast  = -0.5f * ((const float*)&g_pts[qsb][qbase + QPB - 1])[2];
    const int qb_min = bucket_of(zfirst);
    const int qb_max = bucket_of(zlast);

    // Grow bucket-aligned window (all threads compute identically; smem only).
    int B0 = qb_min, B1 = qb_max + 1;
    while (true) {
        bool grew = false;
        if (B0 > 0 && sstart[B1] - sstart[B0 - 1] <= MAXW) { B0--; grew = true; }
        if (B1 < NBUCK && sstart[B1 + 1] - sstart[B0] <= MAXW) { B1++; grew = true; }
        if (!grew) break;
    }
    int s0 = sstart[B0], e0 = sstart[B1];
    int R = e0 - s0;
    bool cover = true;
    while (R > MAXW && B1 - B0 > 1) { B1--; e0 = sstart[B1]; R = e0 - s0; cover = false; }
    if (R > MAXW) { R = MAXW; e0 = s0 + R; cover = false; }
    const int P = (R + 1) >> 1;

    // Pack refs into pair format.
    for (int p = tid; p < P; p += WTHREADS) {
        int i0 = s0 + 2 * p;
        float4 r0 = __ldg(&refs[i0]);
        float4 r1 = (2 * p + 1 < R) ? __ldg(&refs[i0 + 1])
                                    : make_float4(0.f, 0.f, 0.f, 1e37f);
        shA[p] = make_float4(r0.x, r1.x, r0.y, r1.y);
        shB[p] = make_float4(r0.z, r1.z, r0.w, r1.w);
    }

    // Query registers.
    unsigned long long qx2[QPT], qy2[QPT], qz2[QPT];
    float q2[QPT], qzs[QPT];
    #pragma unroll
    for (int k = 0; k < QPT; k++) {
        float4 qv = __ldg(&g_pts[qsb][qbase + k * WTHREADS + tid]);
        float a = -0.5f * qv.x, c = -0.5f * qv.y, d = -0.5f * qv.z;
        qx2[k] = pack2(a, a);
        qy2[k] = pack2(c, c);
        qz2[k] = pack2(d, d);
        q2[k] = qv.w;
        qzs[k] = d;
    }
    __syncthreads();

    // Dense R3-style scan.
    float mlo[QPT], mhi[QPT];
    #pragma unroll
    for (int k = 0; k < QPT; k++) { mlo[k] = FINF; mhi[k] = FINF; }
    const ulonglong2* __restrict__ A64 = reinterpret_cast<const ulonglong2*>(shA);
    const ulonglong2* __restrict__ B64 = reinterpret_cast<const ulonglong2*>(shB);
    #pragma unroll 4
    for (int j = 0; j < P; j++) {
        ulonglong2 va = A64[j];
        ulonglong2 vb = B64[j];
        #pragma unroll
        for (int k = 0; k < QPT; k++) {
            unsigned long long t =
                ffma2(qx2[k], va.x, ffma2(qy2[k], va.y, ffma2(qz2[k], vb.x, vb.y)));
            float tl, th;
            unpack2(t, tl, th);
            mlo[k] = fminf(mlo[k], tl);
            mhi[k] = fminf(mhi[k], th);
        }
    }

    // Soundness check + store.
    const float eL = ZLO + (float)B0 * BW;
    const float eH = ZLO + (float)B1 * BW;
    #pragma unroll
    for (int k = 0; k < QPT; k++) {
        float best = q2[k] + fminf(mlo[k], mhi[k]);   // NN sq-dist within window
        float gL = fmaxf(qzs[k] - eL, 0.f);
        float gH = fmaxf(eH - qzs[k], 0.f);
        bool okLo = (B0 == 0)     || (gL * gL >= best);
        bool okHi = (B1 == NBUCK) || (gH * gH >= best);
        bool ok = cover && okLo && okHi;
        int qi = qbase + k * WTHREADS + tid;
        g_min[qsb][qi] = best;
        g_flag[qsb][qi] = ok ? 0 : 1;
    }
}

// ---------------- stage 3: exact fixup for flagged queries --------------------
__global__ __launch_bounds__(FTHREADS)
void chamfer_fixup_kernel() {
    const int chunk = blockIdx.x, b = blockIdx.y, dir = blockIdx.z;
    const int qsb = dir * BATCH + b;
    const int rsb = (1 - dir) * BATCH + b;
    const int qi = chunk * FTHREADS + threadIdx.x;
    if (!g_flag[qsb][qi]) return;

    const float4* __restrict__ refs = g_pts[rsb];
    float4 qv = g_pts[qsb][qi];
    const float qx = -0.5f * qv.x, qy = -0.5f * qv.y, qz = -0.5f * qv.z;
    float b0 = FINF, b1 = FINF, b2 = FINF, b3 = FINF;
    #pragma unroll 1
    for (int j = 0; j < NPTS; j += 4) {
        float4 f0 = __ldg(&refs[j]);
        float4 f1 = __ldg(&refs[j + 1]);
        float4 f2 = __ldg(&refs[j + 2]);
        float4 f3 = __ldg(&refs[j + 3]);
        b0 = fminf(b0, fmaf(qx, f0.x, fmaf(qy, f0.y, fmaf(qz, f0.z, f0.w))));
        b1 = fminf(b1, fmaf(qx, f1.x, fmaf(qy, f1.y, fmaf(qz, f1.z, f1.w))));
        b2 = fminf(b2, fmaf(qx, f2.x, fmaf(qy, f2.y, fmaf(qz, f2.z, f2.w))));
        b3 = fminf(b3, fmaf(qx, f3.x, fmaf(qy, f3.y, fmaf(qz, f3.z, f3.w))));
    }
    g_min[qsb][qi] = qv.w + fminf(fminf(b0, b1), fminf(b2, b3));
}

// ---------------- stage 4: reduce ---------------------------------------------
__global__ __launch_bounds__(256)
void chamfer_reduce1_kernel() {
    __shared__ float ws[8];
    const float* base = &g_min[0][0];
    float s = 0.f;
    for (int i = blockIdx.x * 256 + threadIdx.x; i < TOTQ; i += R1BLOCKS * 256)
        s += base[i];
    #pragma unroll
    for (int o = 16; o; o >>= 1) s += __shfl_xor_sync(0xFFFFFFFFu, s, o);
    int lane = threadIdx.x & 31, wid = threadIdx.x >> 5;
    if (lane == 0) ws[wid] = s;
    __syncthreads();
    if (threadIdx.x == 0) {
        float v = 0.f;
        #pragma unroll
        for (int i = 0; i < 8; i++) v += ws[i];
        g_bsum[blockIdx.x] = v;
    }
}

__global__ __launch_bounds__(256)
void chamfer_reduce2_kernel(float* __restrict__ out) {
    __shared__ float ws[8];
    float s = (threadIdx.x < R1BLOCKS) ? g_bsum[threadIdx.x] : 0.f;
    #pragma unroll
    for (int o = 16; o; o >>= 1) s += __shfl_xor_sync(0xFFFFFFFFu, s, o);
    int lane = threadIdx.x & 31, wid = threadIdx.x >> 5;
    if (lane == 0) ws[wid] = s;
    __syncthreads();
    if (threadIdx.x == 0) {
        float v = 0.f;
        #pragma unroll
        for (int i = 0; i < 8; i++) v += ws[i];
        out[0] = v * (1.0f / ((float)BATCH * (float)NPTS));
    }
}

extern "C" void kernel_launch(void* const* d_in, const int* in_sizes, int n_in,
                              void* d_out, int out_size) {
    const float* x = (const float*)d_in[0];
    const float* y = (const float*)d_in[1];
    float* out = (float*)d_out;

    cudaFuncSetAttribute(chamfer_bucketize_kernel,
                         cudaFuncAttributeMaxDynamicSharedMemorySize,
                         3 * NPTS * (int)sizeof(float));

    chamfer_bucketize_kernel<<<dim3(BATCH, 2), BTHREADS,
                               3 * NPTS * sizeof(float)>>>(x, y);
    chamfer_window_kernel<<<dim3(WCHUNKS, BATCH, 2), WTHREADS>>>();
    chamfer_fixup_kernel<<<dim3(NPTS / FTHREADS, BATCH, 2), FTHREADS>>>();
    chamfer_reduce1_kernel<<<R1BLOCKS, 256>>>();
    chamfer_reduce2_kernel<<<1, 256>>>(out);
}

// round 9
// speedup vs baseline: 1.0049x; 1.0049x over previous
#include <cuda_runtime.h>
#include <cuda_bf16.h>
#include <cstdint>

// ChamferDistance: z-bucketed + block-uniform windowed dense NN + COMPACTED
// dense fixup for the (sparse-region) queries whose window min isn't provably
// global. All hot loops are dense fixed-shape FMA streams.

#define BATCH    16
#define NPTS     4096
#define NBUCK    256
#define ZLO      (-4.6f)
#define ZHI      (4.6f)
#define BW       ((ZHI - ZLO) / NBUCK)
#define INVBW    ((float)NBUCK / (ZHI - ZLO))

#define BTHREADS 512
#define WTHREADS 128
#define QPT      2
#define QPB      (WTHREADS * QPT)             // 256 queries per window block
#define WCHUNKS  (NPTS / QPB)                 // 16
#define MAXW     1024                         // window refs cap
#define WPAIR    (MAXW / 2)                   // 512 pairs -> 16 KB
#define FTHREADS 128
#define FCHUNKS  (NPTS / FTHREADS)            // 32 (worst case)
#define TOTQ     (2 * BATCH * NPTS)           // 131072
#define R1BLOCKS 256
#define FINF     __int_as_float(0x7f800000)

__device__ float4 g_pts[2 * BATCH][NPTS];
__device__ int    g_start[2 * BATCH][NBUCK + 1];
__device__ float  g_min[2 * BATCH][NPTS];
__device__ int    g_fcnt[2 * BATCH];
__device__ int    g_flist[2 * BATCH][NPTS];
__device__ float  g_bsum[R1BLOCKS];

__device__ __forceinline__ int bucket_of(float z) {
    int b = (int)floorf((z - ZLO) * INVBW);
    return min(max(b, 0), NBUCK - 1);
}

// ---------- packed f32x2 helpers ----------
__device__ __forceinline__ unsigned long long ffma2(unsigned long long a,
                                                    unsigned long long b,
                                                    unsigned long long c) {
    unsigned long long d;
    asm("fma.rn.f32x2 %0, %1, %2, %3;" : "=l"(d) : "l"(a), "l"(b), "l"(c));
    return d;
}
__device__ __forceinline__ unsigned long long pack2(float lo, float hi) {
    unsigned long long d;
    asm("mov.b64 %0, {%1, %2};" : "=l"(d) : "r"(__float_as_uint(lo)), "r"(__float_as_uint(hi)));
    return d;
}
__device__ __forceinline__ void unpack2(unsigned long long v, float& lo, float& hi) {
    unsigned int l, h;
    asm("mov.b64 {%0, %1}, %2;" : "=r"(l), "=r"(h) : "l"(v));
    lo = __uint_as_float(l);
    hi = __uint_as_float(h);
}

// ---------------- stage 1: bucketize (also zeroes fixup counters) ------------
__global__ __launch_bounds__(BTHREADS)
void chamfer_bucketize_kernel(const float* __restrict__ x,
                              const float* __restrict__ y) {
    extern __shared__ float sm[];                 // px | py | pz
    float* px = sm;
    float* py = sm + NPTS;
    float* pz = sm + 2 * NPTS;
    __shared__ int cnt[NBUCK];
    __shared__ int scan[NBUCK];
    __shared__ int off[NBUCK];

    const int b = blockIdx.x, set = blockIdx.y;
    const float* src = (set == 0 ? x : y) + (size_t)b * NPTS * 3;
    const int sb = set * BATCH + b;
    const int tid = threadIdx.x;

    if (tid == 0) g_fcnt[sb] = 0;                 // reset fixup counter
    for (int i = tid; i < NBUCK; i += BTHREADS) cnt[i] = 0;
    __syncthreads();
    #pragma unroll
    for (int i = tid; i < NPTS; i += BTHREADS) {
        float a = src[3 * i], c = src[3 * i + 1], d = src[3 * i + 2];
        px[i] = a; py[i] = c; pz[i] = d;
        atomicAdd(&cnt[bucket_of(d)], 1);
    }
    __syncthreads();
    if (tid < NBUCK) scan[tid] = cnt[tid];
    #pragma unroll
    for (int o = 1; o < NBUCK; o <<= 1) {
        __syncthreads();
        int v = (tid < NBUCK && tid >= o) ? scan[tid - o] : 0;
        __syncthreads();
        if (tid < NBUCK) scan[tid] += v;
    }
    __syncthreads();
    if (tid < NBUCK) {
        int st = scan[tid] - cnt[tid];
        off[tid] = st;
        g_start[sb][tid] = st;
        if (tid == 0) g_start[sb][NBUCK] = NPTS;
    }
    __syncthreads();
    #pragma unroll
    for (int i = tid; i < NPTS; i += BTHREADS) {
        float a = px[i], c = py[i], d = pz[i];
        int pos = atomicAdd(&off[bucket_of(d)], 1);
        g_pts[sb][pos] = make_float4(-2.f * a, -2.f * c, -2.f * d,
                                     fmaf(a, a, fmaf(c, c, d * d)));
    }
}

// ---------------- stage 2: windowed dense scan + compaction -------------------
__global__ __launch_bounds__(WTHREADS)
void chamfer_window_kernel() {
    __shared__ float4 shA[WPAIR];   // (-2x0,-2x1,-2y0,-2y1)
    __shared__ float4 shB[WPAIR];   // (-2z0,-2z1, n0,  n1)
    __shared__ int sstart[NBUCK + 1];

    const int chunk = blockIdx.x, b = blockIdx.y, dir = blockIdx.z;
    const int qsb = dir * BATCH + b;
    const int rsb = (1 - dir) * BATCH + b;
    const float4* __restrict__ refs = g_pts[rsb];
    const int tid = threadIdx.x;

    for (int i = tid; i <= NBUCK; i += WTHREADS) sstart[i] = g_start[rsb][i];
    __syncthreads();

    const int qbase = chunk * QPB;
    const float zfirst = -0.5f * ((const float*)&g_pts[qsb][qbase])[2];
    const float zlast  = -0.5f * ((const float*)&g_pts[qsb][qbase + QPB - 1])[2];
    const int qb_min = bucket_of(zfirst);
    const int qb_max = bucket_of(zlast);

    // Grow bucket-aligned window (uniform across threads; smem only).
    int B0 = qb_min, B1 = qb_max + 1;
    while (true) {
        bool grew = false;
        if (B0 > 0 && sstart[B1] - sstart[B0 - 1] <= MAXW) { B0--; grew = true; }
        if (B1 < NBUCK && sstart[B1 + 1] - sstart[B0] <= MAXW) { B1++; grew = true; }
        if (!grew) break;
    }
    int s0 = sstart[B0], e0 = sstart[B1];
    int R = e0 - s0;
    bool cover = true;
    while (R > MAXW && B1 - B0 > 1) { B1--; e0 = sstart[B1]; R = e0 - s0; cover = false; }
    if (R > MAXW) { R = MAXW; e0 = s0 + R; cover = false; }
    const int P = (R + 1) >> 1;

    for (int p = tid; p < P; p += WTHREADS) {
        int i0 = s0 + 2 * p;
        float4 r0 = __ldg(&refs[i0]);
        float4 r1 = (2 * p + 1 < R) ? __ldg(&refs[i0 + 1])
                                    : make_float4(0.f, 0.f, 0.f, 1e37f);
        shA[p] = make_float4(r0.x, r1.x, r0.y, r1.y);
        shB[p] = make_float4(r0.z, r1.z, r0.w, r1.w);
    }

    unsigned long long qx2[QPT], qy2[QPT], qz2[QPT];
    float q2[QPT], qzs[QPT];
    #pragma unroll
    for (int k = 0; k < QPT; k++) {
        float4 qv = __ldg(&g_pts[qsb][qbase + k * WTHREADS + tid]);
        float a = -0.5f * qv.x, c = -0.5f * qv.y, d = -0.5f * qv.z;
        qx2[k] = pack2(a, a);
        qy2[k] = pack2(c, c);
        qz2[k] = pack2(d, d);
        q2[k] = qv.w;
        qzs[k] = d;
    }
    __syncthreads();

    float mlo[QPT], mhi[QPT];
    #pragma unroll
    for (int k = 0; k < QPT; k++) { mlo[k] = FINF; mhi[k] = FINF; }
    const ulonglong2* __restrict__ A64 = reinterpret_cast<const ulonglong2*>(shA);
    const ulonglong2* __restrict__ B64 = reinterpret_cast<const ulonglong2*>(shB);
    #pragma unroll 4
    for (int j = 0; j < P; j++) {
        ulonglong2 va = A64[j];
        ulonglong2 vb = B64[j];
        #pragma unroll
        for (int k = 0; k < QPT; k++) {
            unsigned long long t =
                ffma2(qx2[k], va.x, ffma2(qy2[k], va.y, ffma2(qz2[k], vb.x, vb.y)));
            float tl, th;
            unpack2(t, tl, th);
            mlo[k] = fminf(mlo[k], tl);
            mhi[k] = fminf(mhi[k], th);
        }
    }

    // Soundness check + store; flagged queries go to the compacted list.
    const float eL = ZLO + (float)B0 * BW;
    const float eH = ZLO + (float)B1 * BW;
    #pragma unroll
    for (int k = 0; k < QPT; k++) {
        float best = q2[k] + fminf(mlo[k], mhi[k]);
        float gL = fmaxf(qzs[k] - eL, 0.f);
        float gH = fmaxf(eH - qzs[k], 0.f);
        bool okLo = (B0 == 0)     || (gL * gL >= best);
        bool okHi = (B1 == NBUCK) || (gH * gH >= best);
        bool ok = cover && okLo && okHi;
        int qi = qbase + k * WTHREADS + tid;
        g_min[qsb][qi] = best;
        if (!ok) {
            int pos = atomicAdd(&g_fcnt[qsb], 1);
            g_flist[qsb][pos] = qi;
        }
    }
}

// ---------------- stage 3: DENSE exact fixup over compacted queries ----------
__global__ __launch_bounds__(FTHREADS)
void chamfer_fixup_kernel() {
    const int b = blockIdx.y, dir = blockIdx.z;
    const int qsb = dir * BATCH + b;
    const int rsb = (1 - dir) * BATCH + b;
    const int c = g_fcnt[qsb];
    const int base = blockIdx.x * FTHREADS;
    if (base >= c) return;                        // inactive block: free exit

    const int idx = base + threadIdx.x;
    const bool valid = idx < c;
    const int qi = valid ? g_flist[qsb][idx] : g_flist[qsb][base];

    const float4* __restrict__ refs = g_pts[rsb];
    float4 qv = g_pts[qsb][qi];
    const float qx = -0.5f * qv.x, qy = -0.5f * qv.y, qz = -0.5f * qv.z;
    float b0 = FINF, b1 = FINF, b2 = FINF, b3 = FINF;
    #pragma unroll 2
    for (int j = 0; j < NPTS; j += 4) {
        float4 f0 = __ldg(&refs[j]);
        float4 f1 = __ldg(&refs[j + 1]);
        float4 f2 = __ldg(&refs[j + 2]);
        float4 f3 = __ldg(&refs[j + 3]);
        b0 = fminf(b0, fmaf(qx, f0.x, fmaf(qy, f0.y, fmaf(qz, f0.z, f0.w))));
        b1 = fminf(b1, fmaf(qx, f1.x, fmaf(qy, f1.y, fmaf(qz, f1.z, f1.w))));
        b2 = fminf(b2, fmaf(qx, f2.x, fmaf(qy, f2.y, fmaf(qz, f2.z, f2.w))));
        b3 = fminf(b3, fmaf(qx, f3.x, fmaf(qy, f3.y, fmaf(qz, f3.z, f3.w))));
    }
    if (valid)
        g_min[qsb][qi] = qv.w + fminf(fminf(b0, b1), fminf(b2, b3));
}

// ---------------- stage 4: reduce ---------------------------------------------
__global__ __launch_bounds__(256)
void chamfer_reduce1_kernel() {
    __shared__ float ws[8];
    const float4* base = (const float4*)&g_min[0][0];
    float s = 0.f;
    for (int i = blockIdx.x * 256 + threadIdx.x; i < TOTQ / 4; i += R1BLOCKS * 256) {
        float4 v = base[i];
        s += (v.x + v.y) + (v.z + v.w);
    }
    #pragma unroll
    for (int o = 16; o; o >>= 1) s += __shfl_xor_sync(0xFFFFFFFFu, s, o);
    int lane = threadIdx.x & 31, wid = threadIdx.x >> 5;
    if (lane == 0) ws[wid] = s;
    __syncthreads();
    if (threadIdx.x == 0) {
        float v = 0.f;
        #pragma unroll
        for (int i = 0; i < 8; i++) v += ws[i];
        g_bsum[blockIdx.x] = v;
    }
}

__global__ __launch_bounds__(256)
void chamfer_reduce2_kernel(float* __restrict__ out) {
    __shared__ float ws[8];
    float s = (threadIdx.x < R1BLOCKS) ? g_bsum[threadIdx.x] : 0.f;
    #pragma unroll
    for (int o = 16; o; o >>= 1) s += __shfl_xor_sync(0xFFFFFFFFu, s, o);
    int lane = threadIdx.x & 31, wid = threadIdx.x >> 5;
    if (lane == 0) ws[wid] = s;
    __syncthreads();
    if (threadIdx.x == 0) {
        float v = 0.f;
        #pragma unroll
        for (int i = 0; i < 8; i++) v += ws[i];
        out[0] = v * (1.0f / ((float)BATCH * (float)NPTS));
    }
}

extern "C" void kernel_launch(void* const* d_in, const int* in_sizes, int n_in,
                              void* d_out, int out_size) {
    const float* x = (const float*)d_in[0];
    const float* y = (const float*)d_in[1];
    float* out = (float*)d_out;

    cudaFuncSetAttribute(chamfer_bucketize_kernel,
                         cudaFuncAttributeMaxDynamicSharedMemorySize,
                         3 * NPTS * (int)sizeof(float));

    chamfer_bucketize_kernel<<<dim3(BATCH, 2), BTHREADS,
                               3 * NPTS * sizeof(float)>>>(x, y);
    chamfer_window_kernel<<<dim3(WCHUNKS, BATCH, 2), WTHREADS>>>();
    chamfer_fixup_kernel<<<dim3(FCHUNKS, BATCH, 2), FTHREADS>>>();
    chamfer_reduce1_kernel<<<R1BLOCKS, 256>>>();
    chamfer_reduce2_kernel<<<1, 256>>>(out);
}

// round 11
// speedup vs baseline: 3.5550x; 3.5376x over previous
#include <cuda_runtime.h>
#include <cuda_bf16.h>
#include <cstdint>

// ChamferDistance: dense all-pairs NN via packed f32x2 FMA.
// d(q,r) = ||q||^2 + dot4((qx,qy,qz,1), (-2rx,-2ry,-2rz,||r||^2))
// QPT=4 queries/thread, SPLITS=16 ref slabs (min-combined in reduce).

#define BATCH    16
#define NPTS     4096
#define DIRS     2
#define THREADS  128
#define QPT      4                        // queries per thread
#define QBLK     (THREADS * QPT)          // 512 queries per block
#define QTILES   (NPTS / QBLK)            // 8
#define SPLITS   16                       // ref slabs
#define RTILE    (NPTS / SPLITS)          // 256 refs per block
#define RPAIRS   (RTILE / 2)              // 128 packed pairs (4 KB smem)
#define TOTQ     (DIRS * BATCH * NPTS)    // 131072
#define R1BLOCKS 256
#define FINF     __int_as_float(0x7f800000)

__device__ float g_part[SPLITS][TOTQ];    // per-slab partial NN sq-dists (8 MB)
__device__ float g_bsum[R1BLOCKS];

// ---------- packed f32x2 helpers ----------
__device__ __forceinline__ unsigned long long ffma2(unsigned long long a,
                                                    unsigned long long b,
                                                    unsigned long long c) {
    unsigned long long d;
    asm("fma.rn.f32x2 %0, %1, %2, %3;" : "=l"(d) : "l"(a), "l"(b), "l"(c));
    return d;
}
__device__ __forceinline__ unsigned long long pack2(float lo, float hi) {
    unsigned long long d;
    asm("mov.b64 %0, {%1, %2};" : "=l"(d) : "r"(__float_as_uint(lo)), "r"(__float_as_uint(hi)));
    return d;
}
__device__ __forceinline__ void unpack2(unsigned long long v, float& lo, float& hi) {
    unsigned int l, h;
    asm("mov.b64 {%0, %1}, %2;" : "=r"(l), "=r"(h) : "l"(v));
    lo = __uint_as_float(l);
    hi = __uint_as_float(h);
}

// ---------------- main: dense slab scan ---------------------------------------
__global__ __launch_bounds__(THREADS)
void chamfer_main_kernel(const float* __restrict__ x,
                         const float* __restrict__ y) {
    __shared__ float4 shA[RPAIRS];   // (-2x0,-2x1,-2y0,-2y1)
    __shared__ float4 shB[RPAIRS];   // (-2z0,-2z1, n0,  n1)

    const int qt  = blockIdx.x >> 4;          // query tile [0,8)
    const int s   = blockIdx.x & 15;          // ref slab  [0,16)
    const int b   = blockIdx.y;
    const int dir = blockIdx.z;

    const float* q = (dir == 0) ? x : y;
    const float* r = (dir == 0) ? y : x;
    const float* rbase = r + ((size_t)b * NPTS + s * RTILE) * 3;
    const int tid = threadIdx.x;

    // Load + transform slab refs (1 pair per thread).
    if (tid < RPAIRS) {
        const float* rp = rbase + (size_t)(2 * tid) * 3;
        float a0 = rp[0], a1 = rp[1], a2 = rp[2];
        float b0 = rp[3], b1 = rp[4], b2 = rp[5];
        float na = fmaf(a0, a0, fmaf(a1, a1, a2 * a2));
        float nb = fmaf(b0, b0, fmaf(b1, b1, b2 * b2));
        shA[tid] = make_float4(-2.0f * a0, -2.0f * b0, -2.0f * a1, -2.0f * b1);
        shB[tid] = make_float4(-2.0f * a2, -2.0f * b2, na, nb);
    }

    // Query registers (QPT=4).
    unsigned long long qx2[QPT], qy2[QPT], qz2[QPT];
    float q2[QPT];
    #pragma unroll
    for (int k = 0; k < QPT; k++) {
        int qi = qt * QBLK + k * THREADS + tid;
        const float* qp = q + ((size_t)b * NPTS + qi) * 3;
        float a = qp[0], c = qp[1], d = qp[2];
        qx2[k] = pack2(a, a);
        qy2[k] = pack2(c, c);
        qz2[k] = pack2(d, d);
        q2[k] = fmaf(a, a, fmaf(c, c, d * d));
    }

    __syncthreads();

    float mlo[QPT], mhi[QPT];
    #pragma unroll
    for (int k = 0; k < QPT; k++) { mlo[k] = FINF; mhi[k] = FINF; }

    const ulonglong2* __restrict__ A64 = reinterpret_cast<const ulonglong2*>(shA);
    const ulonglong2* __restrict__ B64 = reinterpret_cast<const ulonglong2*>(shB);

    #pragma unroll 8
    for (int j = 0; j < RPAIRS; j++) {
        ulonglong2 va = A64[j];   // .x = xpair, .y = ypair
        ulonglong2 vb = B64[j];   // .x = zpair, .y = n2pair
        #pragma unroll
        for (int k = 0; k < QPT; k++) {
            unsigned long long t =
                ffma2(qx2[k], va.x, ffma2(qy2[k], va.y, ffma2(qz2[k], vb.x, vb.y)));
            float tl, th;
            unpack2(t, tl, th);
            mlo[k] = fminf(mlo[k], tl);
            mhi[k] = fminf(mhi[k], th);
        }
    }

    // Plain store of per-slab partial (no atomics, no init).
    #pragma unroll
    for (int k = 0; k < QPT; k++) {
        int qi = qt * QBLK + k * THREADS + tid;
        g_part[s][(size_t)dir * BATCH * NPTS + (size_t)b * NPTS + qi] =
            q2[k] + fminf(mlo[k], mhi[k]);
    }
}

// ---------------- stage 2: min over slabs + block sums ------------------------
__global__ __launch_bounds__(256)
void chamfer_reduce1_kernel() {
    __shared__ float ws[8];
    float s = 0.f;
    for (int i = blockIdx.x * 256 + threadIdx.x; i < TOTQ; i += R1BLOCKS * 256) {
        float m = g_part[0][i];
        #pragma unroll
        for (int p = 1; p < SPLITS; p++) m = fminf(m, g_part[p][i]);
        s += m;
    }
    #pragma unroll
    for (int o = 16; o; o >>= 1) s += __shfl_xor_sync(0xFFFFFFFFu, s, o);
    int lane = threadIdx.x & 31, wid = threadIdx.x >> 5;
    if (lane == 0) ws[wid] = s;
    __syncthreads();
    if (threadIdx.x == 0) {
        float v = 0.f;
        #pragma unroll
        for (int i = 0; i < 8; i++) v += ws[i];
        g_bsum[blockIdx.x] = v;
    }
}

// ---------------- stage 3: final sum ------------------------------------------
__global__ __launch_bounds__(256)
void chamfer_reduce2_kernel(float* __restrict__ out) {
    __shared__ float ws[8];
    float s = (threadIdx.x < R1BLOCKS) ? g_bsum[threadIdx.x] : 0.f;
    #pragma unroll
    for (int o = 16; o; o >>= 1) s += __shfl_xor_sync(0xFFFFFFFFu, s, o);
    int lane = threadIdx.x & 31, wid = threadIdx.x >> 5;
    if (lane == 0) ws[wid] = s;
    __syncthreads();
    if (threadIdx.x == 0) {
        float v = 0.f;
        #pragma unroll
        for (int i = 0; i < 8; i++) v += ws[i];
        out[0] = v * (1.0f / ((float)BATCH * (float)NPTS));
    }
}

extern "C" void kernel_launch(void* const* d_in, const int* in_sizes, int n_in,
                              void* d_out, int out_size) {
    const float* x = (const float*)d_in[0];
    const float* y = (const float*)d_in[1];
    float* out = (float*)d_out;

    dim3 grid(QTILES * SPLITS, BATCH, DIRS);   // 128 x 16 x 2 = 4096 blocks
    chamfer_main_kernel<<<grid, THREADS>>>(x, y);

    chamfer_reduce1_kernel<<<R1BLOCKS, 256>>>();
    chamfer_reduce2_kernel<<<1, 256>>>(out);
}